// round 7
// baseline (speedup 1.0000x reference)
#include <cuda_runtime.h>
#include <cstdint>

#define NB   2
#define NS   2048
#define NE   1024
#define NH   16
#define HD   64
#define MTOK (NB * NS)      // 4096
#define NQKV (3 * NE)       // 3072

// Scratch (allocation-free rule: __device__ globals)
__device__ float g_qkv[(size_t)MTOK * NQKV];   // 48 MB
__device__ float g_ctx[(size_t)MTOK * NE];     // 16 MB

__device__ __forceinline__ uint32_t f2tf(float x) {
    uint32_t r;
    asm("cvt.rna.tf32.f32 %0, %1;" : "=r"(r) : "f"(x));
    return r;
}

__device__ __forceinline__ void mma_tf32(float* c, const uint32_t* a, const uint32_t* b) {
    asm volatile(
        "mma.sync.aligned.m16n8k8.row.col.f32.tf32.tf32.f32 "
        "{%0,%1,%2,%3}, {%4,%5,%6,%7}, {%8,%9}, {%0,%1,%2,%3};"
        : "+f"(c[0]), "+f"(c[1]), "+f"(c[2]), "+f"(c[3])
        : "r"(a[0]), "r"(a[1]), "r"(a[2]), "r"(a[3]),
          "r"(b[0]), "r"(b[1]));
}

// hi/lo split: x = hi + lo, hi = tf32(x), lo = tf32(x - hi).  3-term mma
// (hi*hi + hi*lo + lo*hi) recovers ~fp32 GEMM accuracy.
__device__ __forceinline__ void split_tf(float x, uint32_t& hi, uint32_t& lo) {
    hi = f2tf(x);
    lo = f2tf(x - __uint_as_float(hi));
}

// ---------------------------------------------------------------------------
// GEMM: C[M,N] = A[M,K] @ B[N,K]^T + bias[N]  via 3xTF32 mma.sync.m16n8k8
// 128x128 CTA tile, BK=8, 256 threads (8 warps as 4(M) x 2(N)).
// Double-buffered smem (hi+lo planes); tf32 split at smem-store.
// ---------------------------------------------------------------------------
#define GS 136
__device__ __forceinline__ void gemm_body(const float* __restrict__ A,
                                          const float* __restrict__ B,
                                          const float* __restrict__ bias,
                                          float* __restrict__ C,
                                          int N, int K)
{
    __shared__ __align__(16) uint32_t AsH[2][8][GS];
    __shared__ __align__(16) uint32_t AsL[2][8][GS];
    __shared__ __align__(16) uint32_t BsH[2][8][GS];
    __shared__ __align__(16) uint32_t BsL[2][8][GS];

    const int tid  = threadIdx.x;
    const int warp = tid >> 5;
    const int lane = tid & 31;
    const int wm   = warp >> 1;
    const int wn   = warp & 1;
    const int grp  = lane >> 2;
    const int qid  = lane & 3;
    const int mBase = blockIdx.y * 128;
    const int nBase = blockIdx.x * 128;
    const int lr = tid >> 1;
    const int lk = (tid & 1) * 4;

    float acc[2][8][4];
#pragma unroll
    for (int mt = 0; mt < 2; mt++)
#pragma unroll
        for (int nt = 0; nt < 8; nt++)
#pragma unroll
            for (int j = 0; j < 4; j++) acc[mt][nt][j] = 0.0f;

    const float* Ap = A + (size_t)(mBase + lr) * K + lk;
    const float* Bp = B + (size_t)(nBase + lr) * K + lk;

    const int T = K / 8;

    {
        float4 av = *(const float4*)(Ap);
        float4 bv = *(const float4*)(Bp);
        split_tf(av.x, AsH[0][lk + 0][lr], AsL[0][lk + 0][lr]);
        split_tf(av.y, AsH[0][lk + 1][lr], AsL[0][lk + 1][lr]);
        split_tf(av.z, AsH[0][lk + 2][lr], AsL[0][lk + 2][lr]);
        split_tf(av.w, AsH[0][lk + 3][lr], AsL[0][lk + 3][lr]);
        split_tf(bv.x, BsH[0][lk + 0][lr], BsL[0][lk + 0][lr]);
        split_tf(bv.y, BsH[0][lk + 1][lr], BsL[0][lk + 1][lr]);
        split_tf(bv.z, BsH[0][lk + 2][lr], BsL[0][lk + 2][lr]);
        split_tf(bv.w, BsH[0][lk + 3][lr], BsL[0][lk + 3][lr]);
    }
    __syncthreads();

    int buf = 0;
    for (int t = 0; t < T; t++) {
        float4 anext, bnext;
        const bool more = (t + 1 < T);
        if (more) {
            anext = *(const float4*)(Ap + (t + 1) * 8);
            bnext = *(const float4*)(Bp + (t + 1) * 8);
        }

        // A fragments (hi+lo), reused across all nt
        uint32_t afH[2][4], afL[2][4];
#pragma unroll
        for (int mt = 0; mt < 2; mt++) {
            int m = wm * 32 + mt * 16 + grp;
            afH[mt][0] = AsH[buf][qid][m];     afL[mt][0] = AsL[buf][qid][m];
            afH[mt][1] = AsH[buf][qid][m + 8]; afL[mt][1] = AsL[buf][qid][m + 8];
            afH[mt][2] = AsH[buf][qid + 4][m]; afL[mt][2] = AsL[buf][qid + 4][m];
            afH[mt][3] = AsH[buf][qid + 4][m + 8]; afL[mt][3] = AsL[buf][qid + 4][m + 8];
        }

#pragma unroll
        for (int nt = 0; nt < 8; nt++) {
            int n = wn * 64 + nt * 8 + grp;
            uint32_t bfH[2], bfL[2];
            bfH[0] = BsH[buf][qid][n];     bfH[1] = BsH[buf][qid + 4][n];
            bfL[0] = BsL[buf][qid][n];     bfL[1] = BsL[buf][qid + 4][n];
#pragma unroll
            for (int mt = 0; mt < 2; mt++) {
                mma_tf32(acc[mt][nt], afL[mt], bfH);   // lo*hi
                mma_tf32(acc[mt][nt], afH[mt], bfL);   // hi*lo
                mma_tf32(acc[mt][nt], afH[mt], bfH);   // hi*hi
            }
        }

        if (more) {
            int nb = buf ^ 1;
            split_tf(anext.x, AsH[nb][lk + 0][lr], AsL[nb][lk + 0][lr]);
            split_tf(anext.y, AsH[nb][lk + 1][lr], AsL[nb][lk + 1][lr]);
            split_tf(anext.z, AsH[nb][lk + 2][lr], AsL[nb][lk + 2][lr]);
            split_tf(anext.w, AsH[nb][lk + 3][lr], AsL[nb][lk + 3][lr]);
            split_tf(bnext.x, BsH[nb][lk + 0][lr], BsL[nb][lk + 0][lr]);
            split_tf(bnext.y, BsH[nb][lk + 1][lr], BsL[nb][lk + 1][lr]);
            split_tf(bnext.z, BsH[nb][lk + 2][lr], BsL[nb][lk + 2][lr]);
            split_tf(bnext.w, BsH[nb][lk + 3][lr], BsL[nb][lk + 3][lr]);
            __syncthreads();
            buf = nb;
        }
    }

#pragma unroll
    for (int nt = 0; nt < 8; nt++) {
        int col = nBase + wn * 64 + nt * 8 + 2 * qid;
        float2 b2 = *(const float2*)&bias[col];
#pragma unroll
        for (int mt = 0; mt < 2; mt++) {
            int row0 = mBase + wm * 32 + mt * 16 + grp;
            float2 o0, o1;
            o0.x = acc[mt][nt][0] + b2.x;
            o0.y = acc[mt][nt][1] + b2.y;
            o1.x = acc[mt][nt][2] + b2.x;
            o1.y = acc[mt][nt][3] + b2.y;
            *(float2*)&C[(size_t)row0 * N + col]       = o0;
            *(float2*)&C[(size_t)(row0 + 8) * N + col] = o1;
        }
    }
}

__global__ __launch_bounds__(256, 2) void gemm_qkv_kernel(
    const float* __restrict__ x, const float* __restrict__ w,
    const float* __restrict__ bias)
{
    gemm_body(x, w, bias, g_qkv, NQKV, NE);
}

__global__ __launch_bounds__(256, 2) void gemm_out_kernel(
    const float* __restrict__ w, const float* __restrict__ bias,
    float* __restrict__ out)
{
    gemm_body(g_ctx, w, bias, out, NE, NE);
}

// ---------------------------------------------------------------------------
// Flash attention, tf32 tensor cores, causal. BQ=128, BKV=64, HD=64.
// (unchanged from R4/R5 — three independent audits clean)
// ---------------------------------------------------------------------------
#define FBQ 128
#define FBK 64
#define QS_S 68
#define KS_S 76
#define VS_S 76
#define PS_S 68
#define QS_W (FBQ * QS_S)
#define KS_W (FBK * KS_S)
#define VS_W (FBK * VS_S)
#define PS_W (FBQ * PS_S)
#define FL_SMEM_W (QS_W + KS_W + VS_W + PS_W + FBQ)   // 27264 words = 109056 B

__global__ __launch_bounds__(256, 2) void flash_attn_kernel()
{
    extern __shared__ __align__(16) uint32_t fsm[];
    uint32_t* Qs = fsm;                 // [q=128][68]  (d cols)
    uint32_t* Ks = Qs + QS_W;           // [kv=64][76]  (d cols)
    uint32_t* Vs = Ks + KS_W;           // [kv=64][76]  (d cols)
    uint32_t* Ps = Vs + VS_W;           // [q=128][68]  (kv cols)
    float*    Al = (float*)(Ps + PS_W); // [128] per-q alpha / inv-l (warp-private slices)

    const int tid  = threadIdx.x;
    const int warp = tid >> 5;
    const int lane = tid & 31;
    const int grp  = lane >> 2;
    const int qid  = lane & 3;
    const int bh   = blockIdx.y;
    const int b    = bh >> 4;
    const int h    = bh & 15;
    const int qb   = (int)gridDim.x - 1 - (int)blockIdx.x;  // long blocks first
    const int tokBase = b * NS + qb * FBQ;
    const int qw      = warp * 16;                 // warp's first q row (local)
    const float* qkv  = g_qkv;

    // ---- load Q block, pre-scaled, tf32, natural [q][d] ----
#pragma unroll
    for (int i = 0; i < 8; i++) {
        int u  = tid + i * 256;
        int r  = u >> 4;
        int c4 = (u & 15) * 4;
        float4 v = *(const float4*)(qkv + (size_t)(tokBase + r) * NQKV + h * HD + c4);
        uint4 t;
        t.x = f2tf(v.x * 0.125f); t.y = f2tf(v.y * 0.125f);
        t.z = f2tf(v.z * 0.125f); t.w = f2tf(v.w * 0.125f);
        *(uint4*)&Qs[r * QS_S + c4] = t;
    }

    float O[4][2][4];     // [mt(d)][nt(q)][j]  (transposed frags)
    float m_i[2], l_i[2];
    m_i[0] = m_i[1] = -1e30f;
    l_i[0] = l_i[1] = 0.0f;
#pragma unroll
    for (int mt = 0; mt < 4; mt++)
#pragma unroll
        for (int nt = 0; nt < 2; nt++)
#pragma unroll
            for (int j = 0; j < 4; j++) O[mt][nt][j] = 0.0f;

    const int nkb = 2 * qb + 2;
    for (int kb = 0; kb < nkb; kb++) {
        __syncthreads();   // protect Ks/Vs from previous iteration's PV reads

        // ---- load K, V tiles (natural layouts, tf32) ----
#pragma unroll
        for (int i = 0; i < 4; i++) {
            int u  = tid + i * 256;
            int r  = u >> 4;
            int c4 = (u & 15) * 4;
            const float* base = qkv + (size_t)(b * NS + kb * FBK + r) * NQKV + h * HD;
            float4 kv4 = *(const float4*)(base + NE + c4);
            float4 vv4 = *(const float4*)(base + 2 * NE + c4);
            uint4 tk, tv;
            tk.x = f2tf(kv4.x); tk.y = f2tf(kv4.y); tk.z = f2tf(kv4.z); tk.w = f2tf(kv4.w);
            tv.x = f2tf(vv4.x); tv.y = f2tf(vv4.y); tv.z = f2tf(vv4.z); tv.w = f2tf(vv4.w);
            *(uint4*)&Ks[r * KS_S + c4] = tk;
            *(uint4*)&Vs[r * VS_S + c4] = tv;
        }
        __syncthreads();

        // warp has any unmasked kv in this block?
        const bool active = (kb * FBK) <= (qb * FBQ + qw + 15);

        if (active) {
            // ---- S = Q @ K^T ----
            float s[8][4];
#pragma unroll
            for (int nt = 0; nt < 8; nt++)
#pragma unroll
                for (int j = 0; j < 4; j++) s[nt][j] = 0.0f;

#pragma unroll
            for (int ks = 0; ks < 8; ks++) {
                uint32_t a[4];
                a[0] = Qs[(qw + grp)     * QS_S + ks * 8 + qid];
                a[1] = Qs[(qw + grp + 8) * QS_S + ks * 8 + qid];
                a[2] = Qs[(qw + grp)     * QS_S + ks * 8 + qid + 4];
                a[3] = Qs[(qw + grp + 8) * QS_S + ks * 8 + qid + 4];
#pragma unroll
                for (int nt = 0; nt < 8; nt++) {
                    uint32_t bfr[2];
                    bfr[0] = Ks[(nt * 8 + grp) * KS_S + ks * 8 + qid];
                    bfr[1] = Ks[(nt * 8 + grp) * KS_S + ks * 8 + qid + 4];
                    mma_tf32(s[nt], a, bfr);
                }
            }

            // ---- causal mask ----
            const int row0 = qb * FBQ + qw + grp;     // global q rows
            const int row1 = row0 + 8;
            const int colB = kb * FBK;
            if (colB + FBK - 1 > row0) {
#pragma unroll
                for (int nt = 0; nt < 8; nt++) {
                    int col = colB + nt * 8 + 2 * qid;
                    if (col     > row0) s[nt][0] = -1e30f;
                    if (col + 1 > row0) s[nt][1] = -1e30f;
                    if (col     > row1) s[nt][2] = -1e30f;
                    if (col + 1 > row1) s[nt][3] = -1e30f;
                }
            }

            // ---- online softmax (per row-half, quad reduction) ----
#pragma unroll
            for (int hf = 0; hf < 2; hf++) {
                const int j0 = 2 * hf;
                float rmax = s[0][j0];
#pragma unroll
                for (int nt = 0; nt < 8; nt++) {
                    rmax = fmaxf(rmax, s[nt][j0]);
                    rmax = fmaxf(rmax, s[nt][j0 + 1]);
                }
                rmax = fmaxf(rmax, __shfl_xor_sync(0xffffffffu, rmax, 1));
                rmax = fmaxf(rmax, __shfl_xor_sync(0xffffffffu, rmax, 2));

                float mnew  = fmaxf(m_i[hf], rmax);
                float alpha = __expf(m_i[hf] - mnew);
                float lsum  = 0.0f;
#pragma unroll
                for (int nt = 0; nt < 8; nt++) {
                    float p0 = __expf(s[nt][j0]     - mnew);
                    float p1 = __expf(s[nt][j0 + 1] - mnew);
                    s[nt][j0] = p0; s[nt][j0 + 1] = p1;
                    lsum += p0 + p1;
                }
                lsum += __shfl_xor_sync(0xffffffffu, lsum, 1);
                lsum += __shfl_xor_sync(0xffffffffu, lsum, 2);

                l_i[hf] = l_i[hf] * alpha + lsum;
                m_i[hf] = mnew;
                if (qid == 0) Al[qw + grp + hf * 8] = alpha;
            }

            // ---- write P (tf32) to Ps[q][kv] ----
#pragma unroll
            for (int nt = 0; nt < 8; nt++) {
                uint2 p0, p1;
                p0.x = f2tf(s[nt][0]); p0.y = f2tf(s[nt][1]);
                p1.x = f2tf(s[nt][2]); p1.y = f2tf(s[nt][3]);
                *(uint2*)&Ps[(qw + grp)     * PS_S + nt * 8 + 2 * qid] = p0;
                *(uint2*)&Ps[(qw + grp + 8) * PS_S + nt * 8 + 2 * qid] = p1;
            }
        }
        __syncwarp();

        if (active) {
            // ---- rescale O by per-q alpha ----
            float av[2][2];
#pragma unroll
            for (int nt = 0; nt < 2; nt++) {
                av[nt][0] = Al[qw + nt * 8 + 2 * qid];
                av[nt][1] = Al[qw + nt * 8 + 2 * qid + 1];
            }
#pragma unroll
            for (int mt = 0; mt < 4; mt++)
#pragma unroll
                for (int nt = 0; nt < 2; nt++) {
                    O[mt][nt][0] *= av[nt][0];
                    O[mt][nt][1] *= av[nt][1];
                    O[mt][nt][2] *= av[nt][0];
                    O[mt][nt][3] *= av[nt][1];
                }

            // ---- O^T += V^T @ P^T  (A = Vs natural, B = Ps natural) ----
#pragma unroll
            for (int ks = 0; ks < 8; ks++) {
                uint32_t bfr[2][2];
#pragma unroll
                for (int nt = 0; nt < 2; nt++) {
                    bfr[nt][0] = Ps[(qw + nt * 8 + grp) * PS_S + ks * 8 + qid];
                    bfr[nt][1] = Ps[(qw + nt * 8 + grp) * PS_S + ks * 8 + qid + 4];
                }
#pragma unroll
                for (int mt = 0; mt < 4; mt++) {
                    uint32_t a[4];
                    a[0] = Vs[(ks * 8 + qid)     * VS_S + mt * 16 + grp];
                    a[1] = Vs[(ks * 8 + qid)     * VS_S + mt * 16 + grp + 8];
                    a[2] = Vs[(ks * 8 + qid + 4) * VS_S + mt * 16 + grp];
                    a[3] = Vs[(ks * 8 + qid + 4) * VS_S + mt * 16 + grp + 8];
                    mma_tf32(O[mt][0], a, bfr[0]);
                    mma_tf32(O[mt][1], a, bfr[1]);
                }
            }
        }
    }

    // ---- publish 1/l per q (warp-private Al slice), normalize + store ----
    if (qid == 0) {
        Al[qw + grp]     = 1.0f / l_i[0];
        Al[qw + grp + 8] = 1.0f / l_i[1];
    }
    __syncwarp();

    float iv[2][2];
#pragma unroll
    for (int nt = 0; nt < 2; nt++) {
        iv[nt][0] = Al[qw + nt * 8 + 2 * qid];
        iv[nt][1] = Al[qw + nt * 8 + 2 * qid + 1];
    }
#pragma unroll
    for (int mt = 0; mt < 4; mt++)
#pragma unroll
        for (int nt = 0; nt < 2; nt++) {
            int q = tokBase + qw + nt * 8 + 2 * qid;     // global token row
            int d = h * HD + mt * 16 + grp;
            g_ctx[(size_t)q       * NE + d]     = O[mt][nt][0] * iv[nt][0];
            g_ctx[(size_t)(q + 1) * NE + d]     = O[mt][nt][1] * iv[nt][1];
            g_ctx[(size_t)q       * NE + d + 8] = O[mt][nt][2] * iv[nt][0];
            g_ctx[(size_t)(q + 1) * NE + d + 8] = O[mt][nt][3] * iv[nt][1];
        }
}

// ---------------------------------------------------------------------------
extern "C" void kernel_launch(void* const* d_in, const int* in_sizes, int n_in,
                              void* d_out, int out_size)
{
    const float* x     = (const float*)d_in[0];
    const float* qkv_w = (const float*)d_in[1];
    const float* qkv_b = (const float*)d_in[2];
    const float* out_w = (const float*)d_in[3];
    const float* out_b = (const float*)d_in[4];
    float* out = (float*)d_out;

    const int flash_smem = FL_SMEM_W * (int)sizeof(uint32_t);   // 109,056 B
    cudaFuncSetAttribute(flash_attn_kernel,
                         cudaFuncAttributeMaxDynamicSharedMemorySize, flash_smem);

    dim3 blk(256);
    // 1) QKV projection (3xTF32 tensor cores, ~fp32 accuracy)
    gemm_qkv_kernel<<<dim3(NQKV / 128, MTOK / 128), blk>>>(x, qkv_w, qkv_b);
    // 2) causal flash attention per (b, h) (tf32 tensor cores)
    flash_attn_kernel<<<dim3(NS / FBQ, NB * NH), blk, flash_smem>>>();
    // 3) output projection (3xTF32 tensor cores, ~fp32 accuracy)
    gemm_out_kernel<<<dim3(NE / 128, MTOK / 128), blk>>>(out_w, out_b, out);
}

// round 10
// speedup vs baseline: 1.4259x; 1.4259x over previous
#include <cuda_runtime.h>
#include <cstdint>

#define NB   2
#define NS   2048
#define NE   1024
#define NH   16
#define HD   64
#define MTOK (NB * NS)      // 4096
#define NQKV (3 * NE)       // 3072

// Scratch (allocation-free rule: __device__ globals)
__device__ float g_qkv[(size_t)MTOK * NQKV];   // 48 MB
__device__ float g_ctx[(size_t)MTOK * NE];     // 16 MB

__device__ __forceinline__ uint32_t f2tf(float x) {
    uint32_t r;
    asm("cvt.rna.tf32.f32 %0, %1;" : "=r"(r) : "f"(x));
    return r;
}

__device__ __forceinline__ void mma_tf32(float* c, const uint32_t* a, const uint32_t* b) {
    asm volatile(
        "mma.sync.aligned.m16n8k8.row.col.f32.tf32.tf32.f32 "
        "{%0,%1,%2,%3}, {%4,%5,%6,%7}, {%8,%9}, {%0,%1,%2,%3};"
        : "+f"(c[0]), "+f"(c[1]), "+f"(c[2]), "+f"(c[3])
        : "r"(a[0]), "r"(a[1]), "r"(a[2]), "r"(a[3]),
          "r"(b[0]), "r"(b[1]));
}

// ---------------------------------------------------------------------------
// GEMM: C[M,N] = A[M,K] @ B[N,K]^T + bias[N]  via tf32 mma.sync.m16n8k8
// 128x128 CTA tile, BK=8, 256 threads (8 warps as 4(M) x 2(N)).
// Double-buffered smem; tf32 convert at smem-store (rna rounding).
// Plain tf32 (single plane): R7 measurement showed 3xTF32 cost 3x tensor
// work for precision we don't need (measured rel_err 2.18e-4 with margin).
// ---------------------------------------------------------------------------
#define GS 136
__device__ __forceinline__ void gemm_body(const float* __restrict__ A,
                                          const float* __restrict__ B,
                                          const float* __restrict__ bias,
                                          float* __restrict__ C,
                                          int N, int K)
{
    __shared__ __align__(16) uint32_t As[2][8][GS];
    __shared__ __align__(16) uint32_t Bs[2][8][GS];

    const int tid  = threadIdx.x;
    const int warp = tid >> 5;
    const int lane = tid & 31;
    const int wm   = warp >> 1;
    const int wn   = warp & 1;
    const int grp  = lane >> 2;
    const int qid  = lane & 3;
    const int mBase = blockIdx.y * 128;
    const int nBase = blockIdx.x * 128;
    const int lr = tid >> 1;
    const int lk = (tid & 1) * 4;

    float acc[2][8][4];
#pragma unroll
    for (int mt = 0; mt < 2; mt++)
#pragma unroll
        for (int nt = 0; nt < 8; nt++)
#pragma unroll
            for (int j = 0; j < 4; j++) acc[mt][nt][j] = 0.0f;

    const float* Ap = A + (size_t)(mBase + lr) * K + lk;
    const float* Bp = B + (size_t)(nBase + lr) * K + lk;

    const int T = K / 8;

    {
        float4 av = *(const float4*)(Ap);
        float4 bv = *(const float4*)(Bp);
        As[0][lk + 0][lr] = f2tf(av.x); As[0][lk + 1][lr] = f2tf(av.y);
        As[0][lk + 2][lr] = f2tf(av.z); As[0][lk + 3][lr] = f2tf(av.w);
        Bs[0][lk + 0][lr] = f2tf(bv.x); Bs[0][lk + 1][lr] = f2tf(bv.y);
        Bs[0][lk + 2][lr] = f2tf(bv.z); Bs[0][lk + 3][lr] = f2tf(bv.w);
    }
    __syncthreads();

    int buf = 0;
    for (int t = 0; t < T; t++) {
        float4 anext, bnext;
        const bool more = (t + 1 < T);
        if (more) {
            anext = *(const float4*)(Ap + (t + 1) * 8);
            bnext = *(const float4*)(Bp + (t + 1) * 8);
        }

        uint32_t bf[8][2];
#pragma unroll
        for (int nt = 0; nt < 8; nt++) {
            int n = wn * 64 + nt * 8 + grp;
            bf[nt][0] = Bs[buf][qid][n];
            bf[nt][1] = Bs[buf][qid + 4][n];
        }
        uint32_t af[2][4];
#pragma unroll
        for (int mt = 0; mt < 2; mt++) {
            int m = wm * 32 + mt * 16 + grp;
            af[mt][0] = As[buf][qid][m];
            af[mt][1] = As[buf][qid][m + 8];
            af[mt][2] = As[buf][qid + 4][m];
            af[mt][3] = As[buf][qid + 4][m + 8];
        }

#pragma unroll
        for (int mt = 0; mt < 2; mt++)
#pragma unroll
            for (int nt = 0; nt < 8; nt++)
                mma_tf32(acc[mt][nt], af[mt], bf[nt]);

        if (more) {
            int nb = buf ^ 1;
            As[nb][lk + 0][lr] = f2tf(anext.x); As[nb][lk + 1][lr] = f2tf(anext.y);
            As[nb][lk + 2][lr] = f2tf(anext.z); As[nb][lk + 3][lr] = f2tf(anext.w);
            Bs[nb][lk + 0][lr] = f2tf(bnext.x); Bs[nb][lk + 1][lr] = f2tf(bnext.y);
            Bs[nb][lk + 2][lr] = f2tf(bnext.z); Bs[nb][lk + 3][lr] = f2tf(bnext.w);
            __syncthreads();
            buf = nb;
        }
    }

#pragma unroll
    for (int nt = 0; nt < 8; nt++) {
        int col = nBase + wn * 64 + nt * 8 + 2 * qid;
        float2 b2 = *(const float2*)&bias[col];
#pragma unroll
        for (int mt = 0; mt < 2; mt++) {
            int row0 = mBase + wm * 32 + mt * 16 + grp;
            float2 o0, o1;
            o0.x = acc[mt][nt][0] + b2.x;
            o0.y = acc[mt][nt][1] + b2.y;
            o1.x = acc[mt][nt][2] + b2.x;
            o1.y = acc[mt][nt][3] + b2.y;
            *(float2*)&C[(size_t)row0 * N + col]       = o0;
            *(float2*)&C[(size_t)(row0 + 8) * N + col] = o1;
        }
    }
}

__global__ __launch_bounds__(256, 2) void gemm_qkv_kernel(
    const float* __restrict__ x, const float* __restrict__ w,
    const float* __restrict__ bias)
{
    gemm_body(x, w, bias, g_qkv, NQKV, NE);
}

__global__ __launch_bounds__(256, 2) void gemm_out_kernel(
    const float* __restrict__ w, const float* __restrict__ bias,
    float* __restrict__ out)
{
    gemm_body(g_ctx, w, bias, out, NE, NE);
}

// ---------------------------------------------------------------------------
// Flash attention, tf32 tensor cores, causal. BQ=128, BKV=64, HD=64.
// (unchanged — verified passing at rel_err 2.18e-4)
// ---------------------------------------------------------------------------
#define FBQ 128
#define FBK 64
#define QS_S 68
#define KS_S 76
#define VS_S 76
#define PS_S 68
#define QS_W (FBQ * QS_S)
#define KS_W (FBK * KS_S)
#define VS_W (FBK * VS_S)
#define PS_W (FBQ * PS_S)
#define FL_SMEM_W (QS_W + KS_W + VS_W + PS_W + FBQ)   // 27264 words = 109056 B

__global__ __launch_bounds__(256, 2) void flash_attn_kernel()
{
    extern __shared__ __align__(16) uint32_t fsm[];
    uint32_t* Qs = fsm;                 // [q=128][68]  (d cols)
    uint32_t* Ks = Qs + QS_W;           // [kv=64][76]  (d cols)
    uint32_t* Vs = Ks + KS_W;           // [kv=64][76]  (d cols)
    uint32_t* Ps = Vs + VS_W;           // [q=128][68]  (kv cols)
    float*    Al = (float*)(Ps + PS_W); // [128] per-q alpha / inv-l (warp-private slices)

    const int tid  = threadIdx.x;
    const int warp = tid >> 5;
    const int lane = tid & 31;
    const int grp  = lane >> 2;
    const int qid  = lane & 3;
    const int bh   = blockIdx.y;
    const int b    = bh >> 4;
    const int h    = bh & 15;
    const int qb   = (int)gridDim.x - 1 - (int)blockIdx.x;  // long blocks first
    const int tokBase = b * NS + qb * FBQ;
    const int qw      = warp * 16;                 // warp's first q row (local)
    const float* qkv  = g_qkv;

    // ---- load Q block, pre-scaled, tf32, natural [q][d] ----
#pragma unroll
    for (int i = 0; i < 8; i++) {
        int u  = tid + i * 256;
        int r  = u >> 4;
        int c4 = (u & 15) * 4;
        float4 v = *(const float4*)(qkv + (size_t)(tokBase + r) * NQKV + h * HD + c4);
        uint4 t;
        t.x = f2tf(v.x * 0.125f); t.y = f2tf(v.y * 0.125f);
        t.z = f2tf(v.z * 0.125f); t.w = f2tf(v.w * 0.125f);
        *(uint4*)&Qs[r * QS_S + c4] = t;
    }

    float O[4][2][4];     // [mt(d)][nt(q)][j]  (transposed frags)
    float m_i[2], l_i[2];
    m_i[0] = m_i[1] = -1e30f;
    l_i[0] = l_i[1] = 0.0f;
#pragma unroll
    for (int mt = 0; mt < 4; mt++)
#pragma unroll
        for (int nt = 0; nt < 2; nt++)
#pragma unroll
            for (int j = 0; j < 4; j++) O[mt][nt][j] = 0.0f;

    const int nkb = 2 * qb + 2;
    for (int kb = 0; kb < nkb; kb++) {
        __syncthreads();   // protect Ks/Vs from previous iteration's PV reads

        // ---- load K, V tiles (natural layouts, tf32) ----
#pragma unroll
        for (int i = 0; i < 4; i++) {
            int u  = tid + i * 256;
            int r  = u >> 4;
            int c4 = (u & 15) * 4;
            const float* base = qkv + (size_t)(b * NS + kb * FBK + r) * NQKV + h * HD;
            float4 kv4 = *(const float4*)(base + NE + c4);
            float4 vv4 = *(const float4*)(base + 2 * NE + c4);
            uint4 tk, tv;
            tk.x = f2tf(kv4.x); tk.y = f2tf(kv4.y); tk.z = f2tf(kv4.z); tk.w = f2tf(kv4.w);
            tv.x = f2tf(vv4.x); tv.y = f2tf(vv4.y); tv.z = f2tf(vv4.z); tv.w = f2tf(vv4.w);
            *(uint4*)&Ks[r * KS_S + c4] = tk;
            *(uint4*)&Vs[r * VS_S + c4] = tv;
        }
        __syncthreads();

        // warp has any unmasked kv in this block?
        const bool active = (kb * FBK) <= (qb * FBQ + qw + 15);

        if (active) {
            // ---- S = Q @ K^T ----
            float s[8][4];
#pragma unroll
            for (int nt = 0; nt < 8; nt++)
#pragma unroll
                for (int j = 0; j < 4; j++) s[nt][j] = 0.0f;

#pragma unroll
            for (int ks = 0; ks < 8; ks++) {
                uint32_t a[4];
                a[0] = Qs[(qw + grp)     * QS_S + ks * 8 + qid];
                a[1] = Qs[(qw + grp + 8) * QS_S + ks * 8 + qid];
                a[2] = Qs[(qw + grp)     * QS_S + ks * 8 + qid + 4];
                a[3] = Qs[(qw + grp + 8) * QS_S + ks * 8 + qid + 4];
#pragma unroll
                for (int nt = 0; nt < 8; nt++) {
                    uint32_t bfr[2];
                    bfr[0] = Ks[(nt * 8 + grp) * KS_S + ks * 8 + qid];
                    bfr[1] = Ks[(nt * 8 + grp) * KS_S + ks * 8 + qid + 4];
                    mma_tf32(s[nt], a, bfr);
                }
            }

            // ---- causal mask ----
            const int row0 = qb * FBQ + qw + grp;     // global q rows
            const int row1 = row0 + 8;
            const int colB = kb * FBK;
            if (colB + FBK - 1 > row0) {
#pragma unroll
                for (int nt = 0; nt < 8; nt++) {
                    int col = colB + nt * 8 + 2 * qid;
                    if (col     > row0) s[nt][0] = -1e30f;
                    if (col + 1 > row0) s[nt][1] = -1e30f;
                    if (col     > row1) s[nt][2] = -1e30f;
                    if (col + 1 > row1) s[nt][3] = -1e30f;
                }
            }

            // ---- online softmax (per row-half, quad reduction) ----
#pragma unroll
            for (int hf = 0; hf < 2; hf++) {
                const int j0 = 2 * hf;
                float rmax = s[0][j0];
#pragma unroll
                for (int nt = 0; nt < 8; nt++) {
                    rmax = fmaxf(rmax, s[nt][j0]);
                    rmax = fmaxf(rmax, s[nt][j0 + 1]);
                }
                rmax = fmaxf(rmax, __shfl_xor_sync(0xffffffffu, rmax, 1));
                rmax = fmaxf(rmax, __shfl_xor_sync(0xffffffffu, rmax, 2));

                float mnew  = fmaxf(m_i[hf], rmax);
                float alpha = __expf(m_i[hf] - mnew);
                float lsum  = 0.0f;
#pragma unroll
                for (int nt = 0; nt < 8; nt++) {
                    float p0 = __expf(s[nt][j0]     - mnew);
                    float p1 = __expf(s[nt][j0 + 1] - mnew);
                    s[nt][j0] = p0; s[nt][j0 + 1] = p1;
                    lsum += p0 + p1;
                }
                lsum += __shfl_xor_sync(0xffffffffu, lsum, 1);
                lsum += __shfl_xor_sync(0xffffffffu, lsum, 2);

                l_i[hf] = l_i[hf] * alpha + lsum;
                m_i[hf] = mnew;
                if (qid == 0) Al[qw + grp + hf * 8] = alpha;
            }

            // ---- write P (tf32) to Ps[q][kv] ----
#pragma unroll
            for (int nt = 0; nt < 8; nt++) {
                uint2 p0, p1;
                p0.x = f2tf(s[nt][0]); p0.y = f2tf(s[nt][1]);
                p1.x = f2tf(s[nt][2]); p1.y = f2tf(s[nt][3]);
                *(uint2*)&Ps[(qw + grp)     * PS_S + nt * 8 + 2 * qid] = p0;
                *(uint2*)&Ps[(qw + grp + 8) * PS_S + nt * 8 + 2 * qid] = p1;
            }
        }
        __syncwarp();

        if (active) {
            // ---- rescale O by per-q alpha ----
            float av[2][2];
#pragma unroll
            for (int nt = 0; nt < 2; nt++) {
                av[nt][0] = Al[qw + nt * 8 + 2 * qid];
                av[nt][1] = Al[qw + nt * 8 + 2 * qid + 1];
            }
#pragma unroll
            for (int mt = 0; mt < 4; mt++)
#pragma unroll
                for (int nt = 0; nt < 2; nt++) {
                    O[mt][nt][0] *= av[nt][0];
                    O[mt][nt][1] *= av[nt][1];
                    O[mt][nt][2] *= av[nt][0];
                    O[mt][nt][3] *= av[nt][1];
                }

            // ---- O^T += V^T @ P^T  (A = Vs natural, B = Ps natural) ----
#pragma unroll
            for (int ks = 0; ks < 8; ks++) {
                uint32_t bfr[2][2];
#pragma unroll
                for (int nt = 0; nt < 2; nt++) {
                    bfr[nt][0] = Ps[(qw + nt * 8 + grp) * PS_S + ks * 8 + qid];
                    bfr[nt][1] = Ps[(qw + nt * 8 + grp) * PS_S + ks * 8 + qid + 4];
                }
#pragma unroll
                for (int mt = 0; mt < 4; mt++) {
                    uint32_t a[4];
                    a[0] = Vs[(ks * 8 + qid)     * VS_S + mt * 16 + grp];
                    a[1] = Vs[(ks * 8 + qid)     * VS_S + mt * 16 + grp + 8];
                    a[2] = Vs[(ks * 8 + qid + 4) * VS_S + mt * 16 + grp];
                    a[3] = Vs[(ks * 8 + qid + 4) * VS_S + mt * 16 + grp + 8];
                    mma_tf32(O[mt][0], a, bfr[0]);
                    mma_tf32(O[mt][1], a, bfr[1]);
                }
            }
        }
    }

    // ---- publish 1/l per q (warp-private Al slice), normalize + store ----
    if (qid == 0) {
        Al[qw + grp]     = 1.0f / l_i[0];
        Al[qw + grp + 8] = 1.0f / l_i[1];
    }
    __syncwarp();

    float iv[2][2];
#pragma unroll
    for (int nt = 0; nt < 2; nt++) {
        iv[nt][0] = Al[qw + nt * 8 + 2 * qid];
        iv[nt][1] = Al[qw + nt * 8 + 2 * qid + 1];
    }
#pragma unroll
    for (int mt = 0; mt < 4; mt++)
#pragma unroll
        for (int nt = 0; nt < 2; nt++) {
            int q = tokBase + qw + nt * 8 + 2 * qid;     // global token row
            int d = h * HD + mt * 16 + grp;
            g_ctx[(size_t)q       * NE + d]     = O[mt][nt][0] * iv[nt][0];
            g_ctx[(size_t)(q + 1) * NE + d]     = O[mt][nt][1] * iv[nt][1];
            g_ctx[(size_t)q       * NE + d + 8] = O[mt][nt][2] * iv[nt][0];
            g_ctx[(size_t)(q + 1) * NE + d + 8] = O[mt][nt][3] * iv[nt][1];
        }
}

// ---------------------------------------------------------------------------
extern "C" void kernel_launch(void* const* d_in, const int* in_sizes, int n_in,
                              void* d_out, int out_size)
{
    const float* x     = (const float*)d_in[0];
    const float* qkv_w = (const float*)d_in[1];
    const float* qkv_b = (const float*)d_in[2];
    const float* out_w = (const float*)d_in[3];
    const float* out_b = (const float*)d_in[4];
    float* out = (float*)d_out;

    const int flash_smem = FL_SMEM_W * (int)sizeof(uint32_t);   // 109,056 B
    cudaFuncSetAttribute(flash_attn_kernel,
                         cudaFuncAttributeMaxDynamicSharedMemorySize, flash_smem);

    dim3 blk(256);
    // 1) QKV projection (tf32 tensor cores)
    gemm_qkv_kernel<<<dim3(NQKV / 128, MTOK / 128), blk>>>(x, qkv_w, qkv_b);
    // 2) causal flash attention per (b, h) (tf32 tensor cores)
    flash_attn_kernel<<<dim3(NS / FBQ, NB * NH), blk, flash_smem>>>();
    // 3) output projection (tf32 tensor cores)
    gemm_out_kernel<<<dim3(NE / 128, MTOK / 128), blk>>>(out_w, out_b, out);
}